// round 3
// baseline (speedup 1.0000x reference)
#include <cuda_runtime.h>
#include <math.h>

#define S_LEN  2048
#define BATCH  2
#define DMODEL 1024
#define NHEADS 16
#define DK     64
#define MTOT   (BATCH * S_LEN)   // 4096

typedef unsigned long long u64;

// ---------------- packed f32x2 helpers (Blackwell FFMA2) ------------------
__device__ __forceinline__ void ffma2(u64& d, u64 a, u64 b) {
    asm("fma.rn.f32x2 %0, %1, %2, %3;" : "=l"(d) : "l"(a), "l"(b), "l"(d));
}
__device__ __forceinline__ void fmul2(u64& d, u64 a, u64 b) {
    asm("mul.rn.f32x2 %0, %1, %2;" : "=l"(d) : "l"(a), "l"(b));
}
__device__ __forceinline__ u64 dup2(float x) {
    u64 d; asm("mov.b64 %0, {%1, %1};" : "=l"(d) : "f"(x)); return d;
}
__device__ __forceinline__ float2 up2(u64 d) {
    float lo, hi;
    asm("mov.b64 {%0, %1}, %2;" : "=f"(lo), "=f"(hi) : "l"(d));
    return make_float2(lo, hi);
}

// ---------------- scratch (static device allocations; no cudaMalloc) -----
__device__ float  g_q[(size_t)BATCH * S_LEN * DMODEL];
__device__ float  g_k[(size_t)BATCH * S_LEN * DMODEL];
__device__ float  g_v[(size_t)BATCH * S_LEN * DMODEL];
__device__ float  g_att[(size_t)BATCH * S_LEN * DMODEL];
__device__ float2 g_rope[S_LEN * (DK / 2)];   // [s][i] cos/sin

// ========================================================================
// GEMM:  C[m,n] = sum_k A[m,k] * B[n,k]   (A: MTOTxK row-major, B: NxK)
// M=4096, N=1024, K=1024 fixed. BM=BN=128, BK=16, 256 thr, 8x8 microtile,
// inner product via packed FFMA2 (acc pairs along n).
// ========================================================================
__global__ __launch_bounds__(256) void sgemm_nt(const float* __restrict__ A,
                                                const float* __restrict__ B,
                                                float* __restrict__ C) {
    constexpr int LD = 132;                 // padded smem stride
    __shared__ float As[16 * LD];           // [k][m]
    __shared__ float Bs[16 * LD];           // [k][n]

    const int bn  = blockIdx.x * 128;
    const int bm  = blockIdx.y * 128;
    const int tid = threadIdx.x;
    const int tx  = tid & 15;
    const int ty  = tid >> 4;

    u64 acc2[8][4];
#pragma unroll
    for (int i = 0; i < 8; i++)
#pragma unroll
        for (int j = 0; j < 4; j++) acc2[i][j] = 0ull;

    const float* Ap = A + (size_t)bm * DMODEL;
    const float* Bp = B + (size_t)bn * DMODEL;

    for (int kk = 0; kk < DMODEL; kk += 16) {
#pragma unroll
        for (int q = 0; q < 2; q++) {
            int f   = tid + q * 256;        // 0..511 float4s
            int row = f >> 2;               // 0..127
            int kg  = f & 3;                // 0..3 (16B group within BK)
            float4 av = *(const float4*)(Ap + (size_t)row * DMODEL + kk + kg * 4);
            As[(kg * 4 + 0) * LD + row] = av.x;
            As[(kg * 4 + 1) * LD + row] = av.y;
            As[(kg * 4 + 2) * LD + row] = av.z;
            As[(kg * 4 + 3) * LD + row] = av.w;
            float4 bv = *(const float4*)(Bp + (size_t)row * DMODEL + kk + kg * 4);
            Bs[(kg * 4 + 0) * LD + row] = bv.x;
            Bs[(kg * 4 + 1) * LD + row] = bv.y;
            Bs[(kg * 4 + 2) * LD + row] = bv.z;
            Bs[(kg * 4 + 3) * LD + row] = bv.w;
        }
        __syncthreads();

#pragma unroll
        for (int k = 0; k < 16; k++) {
            float a[8];
            *(float4*)(a)     = *(const float4*)&As[k * LD + ty * 4];
            *(float4*)(a + 4) = *(const float4*)&As[k * LD + 64 + ty * 4];
            ulonglong2 b01 = *(const ulonglong2*)&Bs[k * LD + tx * 4];
            ulonglong2 b23 = *(const ulonglong2*)&Bs[k * LD + 64 + tx * 4];
            u64 bb0 = b01.x, bb1 = b01.y, bb2 = b23.x, bb3 = b23.y;
#pragma unroll
            for (int i = 0; i < 8; i++) {
                u64 ad = dup2(a[i]);
                ffma2(acc2[i][0], ad, bb0);
                ffma2(acc2[i][1], ad, bb1);
                ffma2(acc2[i][2], ad, bb2);
                ffma2(acc2[i][3], ad, bb3);
            }
        }
        __syncthreads();
    }

#pragma unroll
    for (int ar = 0; ar < 2; ar++)
#pragma unroll
        for (int i = 0; i < 4; i++) {
            int row = bm + ar * 64 + ty * 4 + i;
#pragma unroll
            for (int bc = 0; bc < 2; bc++) {
                float2 lo = up2(acc2[ar * 4 + i][bc * 2 + 0]);
                float2 hi = up2(acc2[ar * 4 + i][bc * 2 + 1]);
                float4 v = make_float4(lo.x, lo.y, hi.x, hi.y);
                *(float4*)(C + (size_t)row * DMODEL + bn + bc * 64 + tx * 4) = v;
            }
        }
}

// ========================================================================
// RoPE table: cos/sin of (float)(s) * freq_i, trig evaluated in double of
// the fp32-rounded angle to track the reference numerics.
// ========================================================================
__global__ void rope_table_kernel() {
    int idx = blockIdx.x * blockDim.x + threadIdx.x;   // 65536
    if (idx >= S_LEN * (DK / 2)) return;
    int s = idx >> 5;
    int i = idx & 31;
    float freq = 1.0f / powf(10000.0f, (float)(2 * i) / 64.0f);
    float ang  = (float)s * freq;                      // fp32 like the reference
    double a   = (double)ang;
    g_rope[idx] = make_float2((float)cos(a), (float)sin(a));
}

// Apply RoPE in place. Pairs are adjacent (even,odd) elements; head
// boundaries (64) align with the pair structure, so pair p in the 1024-wide
// row has rotation index i = p % 32.
__global__ void rope_apply_kernel(float* __restrict__ t) {
    int idx = blockIdx.x * blockDim.x + threadIdx.x;   // BATCH*S_LEN*512
    if (idx >= BATCH * S_LEN * (DMODEL / 2)) return;
    int row = idx >> 9;              // b*S + s
    int pp  = idx & 511;
    int s   = row & (S_LEN - 1);
    float2 cs = g_rope[(s << 5) + (pp & 31)];
    float2 v  = ((const float2*)t)[idx];
    float2 r;
    r.x = v.x * cs.x - v.y * cs.y;
    r.y = v.x * cs.y + v.y * cs.x;
    ((float2*)t)[idx] = r;
}

// ========================================================================
// Flash attention, fp32, causal. BM=BN=64, Dk=64, 256 threads.
// Q/K transposed in smem ([d][m], stride 64); QK^T and PV inner products
// via packed FFMA2 (pairs along the n/j axis).
// ========================================================================
__global__ __launch_bounds__(256) void flash_attn(const float* __restrict__ Qg,
                                                  const float* __restrict__ Kg,
                                                  const float* __restrict__ Vg,
                                                  float* __restrict__ Og) {
    extern __shared__ float sm[];
    float* Qt = sm;                  // [64][64]  d-major
    float* Kt = sm + 4096;           // [64][64]  d-major
    float* Vs = sm + 8192;           // [64][64]  n-major
    float* Ps = sm + 12288;          // [64][68]  m-major, padded

    const int qt  = gridDim.x - 1 - blockIdx.x;   // long blocks first
    const int h   = blockIdx.y;
    const int b   = blockIdx.z;
    const int tid = threadIdx.x;
    const int tx  = tid & 15;
    const int ty  = tid >> 4;
    const size_t base = ((size_t)b * S_LEN) * DMODEL + h * DK;
    const int q0 = qt * 64;

    // load Q transposed
#pragma unroll
    for (int p = 0; p < 4; p++) {
        int f = tid + p * 256;
        int m = f & 63, kg = f >> 6;
        float4 v = *(const float4*)(Qg + base + (size_t)(q0 + m) * DMODEL + kg * 4);
        Qt[(kg * 4 + 0) * 64 + m] = v.x;
        Qt[(kg * 4 + 1) * 64 + m] = v.y;
        Qt[(kg * 4 + 2) * 64 + m] = v.z;
        Qt[(kg * 4 + 3) * 64 + m] = v.w;
    }

    u64 o2[4][2];
    float m_i[4], l_i[4];
#pragma unroll
    for (int i = 0; i < 4; i++) {
        m_i[i] = -INFINITY;
        l_i[i] = 0.f;
        o2[i][0] = 0ull;
        o2[i][1] = 0ull;
    }
    const float scale = 0.125f;   // 1/sqrt(64)

    for (int kt = 0; kt <= qt; kt++) {
        const int k0 = kt * 64;
        __syncthreads();   // prior PV reads of Vs/Ps done
#pragma unroll
        for (int p = 0; p < 4; p++) {
            int f = tid + p * 256;
            int n = f & 63, kg = f >> 6;
            float4 kv = *(const float4*)(Kg + base + (size_t)(k0 + n) * DMODEL + kg * 4);
            Kt[(kg * 4 + 0) * 64 + n] = kv.x;
            Kt[(kg * 4 + 1) * 64 + n] = kv.y;
            Kt[(kg * 4 + 2) * 64 + n] = kv.z;
            Kt[(kg * 4 + 3) * 64 + n] = kv.w;
            int n2 = f >> 4, c = (f & 15) * 4;
            *(float4*)&Vs[n2 * 64 + c] =
                *(const float4*)(Vg + base + (size_t)(k0 + n2) * DMODEL + c);
        }
        __syncthreads();

        u64 s2[4][2];
#pragma unroll
        for (int i = 0; i < 4; i++) { s2[i][0] = 0ull; s2[i][1] = 0ull; }

#pragma unroll 4
        for (int d = 0; d < 64; d++) {
            float qa[4];
            *(float4*)qa = *(const float4*)&Qt[d * 64 + ty * 4];
            ulonglong2 kb = *(const ulonglong2*)&Kt[d * 64 + tx * 4];
#pragma unroll
            for (int i = 0; i < 4; i++) {
                u64 qd = dup2(qa[i]);
                ffma2(s2[i][0], qd, kb.x);
                ffma2(s2[i][1], qd, kb.y);
            }
        }

        const bool diag = (kt == qt);
#pragma unroll
        for (int i = 0; i < 4; i++) {
            float s[4];
            float2 lo = up2(s2[i][0]);
            float2 hi = up2(s2[i][1]);
            s[0] = lo.x; s[1] = lo.y; s[2] = hi.x; s[3] = hi.y;
#pragma unroll
            for (int j = 0; j < 4; j++) {
                s[j] *= scale;
                if (diag && (k0 + tx * 4 + j > q0 + ty * 4 + i)) s[j] = -INFINITY;
            }
            float lm = fmaxf(fmaxf(s[0], s[1]), fmaxf(s[2], s[3]));
#pragma unroll
            for (int off = 8; off; off >>= 1)
                lm = fmaxf(lm, __shfl_xor_sync(0xffffffffu, lm, off, 16));
            float newm = fmaxf(m_i[i], lm);
            float corr = __expf(m_i[i] - newm);
            float pr[4];
            float rs = 0.f;
#pragma unroll
            for (int j = 0; j < 4; j++) {
                pr[j] = __expf(s[j] - newm);
                rs += pr[j];
            }
#pragma unroll
            for (int off = 8; off; off >>= 1)
                rs += __shfl_xor_sync(0xffffffffu, rs, off, 16);
            l_i[i] = l_i[i] * corr + rs;
            m_i[i] = newm;
            u64 cd = dup2(corr);
            fmul2(o2[i][0], o2[i][0], cd);
            fmul2(o2[i][1], o2[i][1], cd);
            *(float4*)&Ps[(ty * 4 + i) * 68 + tx * 4] =
                make_float4(pr[0], pr[1], pr[2], pr[3]);
        }
        __syncthreads();

#pragma unroll 2
        for (int n4 = 0; n4 < 64; n4 += 4) {
            float pv[4][4];
#pragma unroll
            for (int i = 0; i < 4; i++)
                *(float4*)pv[i] = *(const float4*)&Ps[(ty * 4 + i) * 68 + n4];
#pragma unroll
            for (int t = 0; t < 4; t++) {
                ulonglong2 vvp = *(const ulonglong2*)&Vs[(n4 + t) * 64 + tx * 4];
#pragma unroll
                for (int i = 0; i < 4; i++) {
                    u64 pd = dup2(pv[i][t]);
                    ffma2(o2[i][0], pd, vvp.x);
                    ffma2(o2[i][1], pd, vvp.y);
                }
            }
        }
    }

#pragma unroll
    for (int i = 0; i < 4; i++) {
        float inv = 1.0f / l_i[i];
        float2 lo = up2(o2[i][0]);
        float2 hi = up2(o2[i][1]);
        float4 r = make_float4(lo.x * inv, lo.y * inv, hi.x * inv, hi.y * inv);
        *(float4*)(Og + base + (size_t)(q0 + ty * 4 + i) * DMODEL + tx * 4) = r;
    }
}

// ========================================================================
extern "C" void kernel_launch(void* const* d_in, const int* in_sizes, int n_in,
                              void* d_out, int out_size) {
    (void)in_sizes; (void)n_in; (void)out_size;
    const float* x  = (const float*)d_in[0];
    const float* Wq = (const float*)d_in[1];
    const float* Wk = (const float*)d_in[2];
    const float* Wv = (const float*)d_in[3];
    const float* Wo = (const float*)d_in[4];
    float* out = (float*)d_out;

    float *q, *k, *v, *att;
    cudaGetSymbolAddress((void**)&q,   g_q);
    cudaGetSymbolAddress((void**)&k,   g_k);
    cudaGetSymbolAddress((void**)&v,   g_v);
    cudaGetSymbolAddress((void**)&att, g_att);

    dim3 gg(DMODEL / 128, MTOT / 128);   // (8, 32)
    sgemm_nt<<<gg, 256>>>(x, Wq, q);
    sgemm_nt<<<gg, 256>>>(x, Wk, k);
    sgemm_nt<<<gg, 256>>>(x, Wv, v);

    rope_table_kernel<<<(S_LEN * (DK / 2) + 255) / 256, 256>>>();
    rope_apply_kernel<<<(BATCH * S_LEN * (DMODEL / 2) + 255) / 256, 256>>>(q);
    rope_apply_kernel<<<(BATCH * S_LEN * (DMODEL / 2) + 255) / 256, 256>>>(k);

    cudaFuncSetAttribute(flash_attn,
                         cudaFuncAttributeMaxDynamicSharedMemorySize, 66560);
    flash_attn<<<dim3(S_LEN / 64, NHEADS, BATCH), 256, 66560>>>(q, k, v, att);

    sgemm_nt<<<gg, 256>>>(att, Wo, out);
}

// round 4
// speedup vs baseline: 1.0206x; 1.0206x over previous
#include <cuda_runtime.h>
#include <math.h>

#define S_LEN  2048
#define BATCH  2
#define DMODEL 1024
#define NHEADS 16
#define DK     64
#define MTOT   (BATCH * S_LEN)   // 4096

// ---------------- scratch (static device allocations; no cudaMalloc) -----
__device__ float  g_q[(size_t)BATCH * S_LEN * DMODEL];
__device__ float  g_k[(size_t)BATCH * S_LEN * DMODEL];
__device__ float  g_v[(size_t)BATCH * S_LEN * DMODEL];
__device__ float  g_att[(size_t)BATCH * S_LEN * DMODEL];
__device__ float2 g_rope[S_LEN * (DK / 2)];   // [s][i] cos/sin

// ---------------- tf32 helpers -------------------------------------------
__device__ __forceinline__ unsigned f2tf(float x) {
    unsigned r;
    asm("cvt.rna.tf32.f32 %0, %1;" : "=r"(r) : "f"(x));
    return r;
}
__device__ __forceinline__ void tf_split(float x, unsigned& hi, unsigned& lo) {
    hi = f2tf(x);
    lo = f2tf(x - __uint_as_float(hi));
}
__device__ __forceinline__ void mma_tf32(float* d, const unsigned* a,
                                         const unsigned* b) {
    asm("mma.sync.aligned.m16n8k8.row.col.f32.tf32.tf32.f32 "
        "{%0,%1,%2,%3}, {%4,%5,%6,%7}, {%8,%9}, {%0,%1,%2,%3};"
        : "+f"(d[0]), "+f"(d[1]), "+f"(d[2]), "+f"(d[3])
        : "r"(a[0]), "r"(a[1]), "r"(a[2]), "r"(a[3]), "r"(b[0]), "r"(b[1]));
}

// ========================================================================
// GEMM:  C[m,n] = sum_k A[m,k] * B[n,k]   (A: MTOTxK row-major, B: NxK)
// Tensor-core 3xTF32. BM=BN=128, BK=32, 256 thr (8 warps, 2x4),
// warp tile 64x32, mma m16n8k8.
// ========================================================================
__global__ __launch_bounds__(256) void sgemm_tc(const float* __restrict__ A,
                                                const float* __restrict__ B,
                                                float* __restrict__ C) {
    constexpr int LD = 132;
    __shared__ float As[32 * LD];     // [k][m]
    __shared__ float Bs[32 * LD];     // [k][n]

    const int bn   = blockIdx.x * 128;
    const int bm   = blockIdx.y * 128;
    const int tid  = threadIdx.x;
    const int lane = tid & 31;
    const int wid  = tid >> 5;
    const int wm   = wid >> 2;        // 0..1
    const int wn   = wid & 3;         // 0..3
    const int g    = lane >> 2;       // 0..7
    const int tig  = lane & 3;        // 0..3

    const float* Ap = A + (size_t)bm * DMODEL;
    const float* Bp = B + (size_t)bn * DMODEL;

    float acc[4][4][4];
#pragma unroll
    for (int mt = 0; mt < 4; mt++)
#pragma unroll
        for (int nt = 0; nt < 4; nt++)
#pragma unroll
            for (int e = 0; e < 4; e++) acc[mt][nt][e] = 0.f;

    // gmem staging registers: 4 float4 of A, 4 of B per thread per tile
    float4 pa[4], pb[4];
#pragma unroll
    for (int p = 0; p < 4; p++) {
        int f = tid + p * 256;        // 0..1023
        int m = f >> 3;
        int c = f & 7;
        pa[p] = *(const float4*)(Ap + (size_t)m * DMODEL + c * 4);
        pb[p] = *(const float4*)(Bp + (size_t)m * DMODEL + c * 4);
    }
#pragma unroll
    for (int p = 0; p < 4; p++) {
        int f = tid + p * 256;
        int m = f >> 3;
        int c = f & 7;
        As[(c * 4 + 0) * LD + m] = pa[p].x;
        As[(c * 4 + 1) * LD + m] = pa[p].y;
        As[(c * 4 + 2) * LD + m] = pa[p].z;
        As[(c * 4 + 3) * LD + m] = pa[p].w;
        Bs[(c * 4 + 0) * LD + m] = pb[p].x;
        Bs[(c * 4 + 1) * LD + m] = pb[p].y;
        Bs[(c * 4 + 2) * LD + m] = pb[p].z;
        Bs[(c * 4 + 3) * LD + m] = pb[p].w;
    }
    __syncthreads();

    for (int kk = 0; kk < DMODEL; kk += 32) {
        const bool more = (kk + 32 < DMODEL);
        if (more) {
#pragma unroll
            for (int p = 0; p < 4; p++) {
                int f = tid + p * 256;
                int m = f >> 3;
                int c = f & 7;
                pa[p] = *(const float4*)(Ap + (size_t)m * DMODEL + kk + 32 + c * 4);
                pb[p] = *(const float4*)(Bp + (size_t)m * DMODEL + kk + 32 + c * 4);
            }
        }

#pragma unroll
        for (int ks = 0; ks < 4; ks++) {
            unsigned Ah[4][4], Al[4][4], Bh[4][2], Bl[4][2];
            const int k0 = ks * 8 + tig;
            const int k1 = ks * 8 + tig + 4;
#pragma unroll
            for (int mt = 0; mt < 4; mt++) {
                const int m0 = wm * 64 + mt * 16 + g;
                tf_split(As[k0 * LD + m0],     Ah[mt][0], Al[mt][0]);
                tf_split(As[k0 * LD + m0 + 8], Ah[mt][1], Al[mt][1]);
                tf_split(As[k1 * LD + m0],     Ah[mt][2], Al[mt][2]);
                tf_split(As[k1 * LD + m0 + 8], Ah[mt][3], Al[mt][3]);
            }
#pragma unroll
            for (int nt = 0; nt < 4; nt++) {
                const int n0 = wn * 32 + nt * 8 + g;
                tf_split(Bs[k0 * LD + n0], Bh[nt][0], Bl[nt][0]);
                tf_split(Bs[k1 * LD + n0], Bh[nt][1], Bl[nt][1]);
            }
#pragma unroll
            for (int mt = 0; mt < 4; mt++)
#pragma unroll
                for (int nt = 0; nt < 4; nt++) {
                    mma_tf32(acc[mt][nt], Ah[mt], Bh[nt]);
                    mma_tf32(acc[mt][nt], Al[mt], Bh[nt]);
                    mma_tf32(acc[mt][nt], Ah[mt], Bl[nt]);
                }
        }

        if (more) {
            __syncthreads();
#pragma unroll
            for (int p = 0; p < 4; p++) {
                int f = tid + p * 256;
                int m = f >> 3;
                int c = f & 7;
                As[(c * 4 + 0) * LD + m] = pa[p].x;
                As[(c * 4 + 1) * LD + m] = pa[p].y;
                As[(c * 4 + 2) * LD + m] = pa[p].z;
                As[(c * 4 + 3) * LD + m] = pa[p].w;
                Bs[(c * 4 + 0) * LD + m] = pb[p].x;
                Bs[(c * 4 + 1) * LD + m] = pb[p].y;
                Bs[(c * 4 + 2) * LD + m] = pb[p].z;
                Bs[(c * 4 + 3) * LD + m] = pb[p].w;
            }
            __syncthreads();
        }
    }

    // epilogue
#pragma unroll
    for (int mt = 0; mt < 4; mt++) {
        const int row = bm + wm * 64 + mt * 16 + g;
#pragma unroll
        for (int nt = 0; nt < 4; nt++) {
            const int col = bn + wn * 32 + nt * 8 + tig * 2;
            *(float2*)(C + (size_t)row * DMODEL + col) =
                make_float2(acc[mt][nt][0], acc[mt][nt][1]);
            *(float2*)(C + (size_t)(row + 8) * DMODEL + col) =
                make_float2(acc[mt][nt][2], acc[mt][nt][3]);
        }
    }
}

// ========================================================================
// RoPE table + apply (unchanged, proven)
// ========================================================================
__global__ void rope_table_kernel() {
    int idx = blockIdx.x * blockDim.x + threadIdx.x;
    if (idx >= S_LEN * (DK / 2)) return;
    int s = idx >> 5;
    int i = idx & 31;
    float freq = 1.0f / powf(10000.0f, (float)(2 * i) / 64.0f);
    float ang  = (float)s * freq;
    double a   = (double)ang;
    g_rope[idx] = make_float2((float)cos(a), (float)sin(a));
}

__global__ void rope_apply_kernel(float* __restrict__ t) {
    int idx = blockIdx.x * blockDim.x + threadIdx.x;
    if (idx >= BATCH * S_LEN * (DMODEL / 2)) return;
    int row = idx >> 9;
    int pp  = idx & 511;
    int s   = row & (S_LEN - 1);
    float2 cs = g_rope[(s << 5) + (pp & 31)];
    float2 v  = ((const float2*)t)[idx];
    float2 r;
    r.x = v.x * cs.x - v.y * cs.y;
    r.y = v.x * cs.y + v.y * cs.x;
    ((float2*)t)[idx] = r;
}

// ========================================================================
// Flash attention, fp32 scalar FFMA (round-1 proven version, __expf).
// ========================================================================
__global__ __launch_bounds__(256) void flash_attn(const float* __restrict__ Qg,
                                                  const float* __restrict__ Kg,
                                                  const float* __restrict__ Vg,
                                                  float* __restrict__ Og) {
    extern __shared__ float sm[];
    float* Qt = sm;                  // [64][64]  d-major
    float* Kt = sm + 4096;           // [64][64]  d-major
    float* Vs = sm + 8192;           // [64][64]  n-major
    float* Ps = sm + 12288;          // [64][68]  m-major, padded

    const int qt  = gridDim.x - 1 - blockIdx.x;
    const int h   = blockIdx.y;
    const int b   = blockIdx.z;
    const int tid = threadIdx.x;
    const int tx  = tid & 15;
    const int ty  = tid >> 4;
    const size_t base = ((size_t)b * S_LEN) * DMODEL + h * DK;
    const int q0 = qt * 64;

#pragma unroll
    for (int p = 0; p < 4; p++) {
        int f = tid + p * 256;
        int m = f & 63, kg = f >> 6;
        float4 v = *(const float4*)(Qg + base + (size_t)(q0 + m) * DMODEL + kg * 4);
        Qt[(kg * 4 + 0) * 64 + m] = v.x;
        Qt[(kg * 4 + 1) * 64 + m] = v.y;
        Qt[(kg * 4 + 2) * 64 + m] = v.z;
        Qt[(kg * 4 + 3) * 64 + m] = v.w;
    }

    float o[4][4];
    float m_i[4], l_i[4];
#pragma unroll
    for (int i = 0; i < 4; i++) {
        m_i[i] = -INFINITY;
        l_i[i] = 0.f;
#pragma unroll
        for (int j = 0; j < 4; j++) o[i][j] = 0.f;
    }
    const float scale = 0.125f;

    for (int kt = 0; kt <= qt; kt++) {
        const int k0 = kt * 64;
        __syncthreads();
#pragma unroll
        for (int p = 0; p < 4; p++) {
            int f = tid + p * 256;
            int n = f & 63, kg = f >> 6;
            float4 kv = *(const float4*)(Kg + base + (size_t)(k0 + n) * DMODEL + kg * 4);
            Kt[(kg * 4 + 0) * 64 + n] = kv.x;
            Kt[(kg * 4 + 1) * 64 + n] = kv.y;
            Kt[(kg * 4 + 2) * 64 + n] = kv.z;
            Kt[(kg * 4 + 3) * 64 + n] = kv.w;
            int n2 = f >> 4, c = (f & 15) * 4;
            *(float4*)&Vs[n2 * 64 + c] =
                *(const float4*)(Vg + base + (size_t)(k0 + n2) * DMODEL + c);
        }
        __syncthreads();

        float s[4][4];
#pragma unroll
        for (int i = 0; i < 4; i++)
#pragma unroll
            for (int j = 0; j < 4; j++) s[i][j] = 0.f;

#pragma unroll 4
        for (int d = 0; d < 64; d++) {
            float qa[4], kb[4];
            *(float4*)qa = *(const float4*)&Qt[d * 64 + ty * 4];
            *(float4*)kb = *(const float4*)&Kt[d * 64 + tx * 4];
#pragma unroll
            for (int i = 0; i < 4; i++)
#pragma unroll
                for (int j = 0; j < 4; j++) s[i][j] += qa[i] * kb[j];
        }

        const bool diag = (kt == qt);
#pragma unroll
        for (int i = 0; i < 4; i++) {
#pragma unroll
            for (int j = 0; j < 4; j++) {
                s[i][j] *= scale;
                if (diag && (k0 + tx * 4 + j > q0 + ty * 4 + i)) s[i][j] = -INFINITY;
            }
            float lm = fmaxf(fmaxf(s[i][0], s[i][1]), fmaxf(s[i][2], s[i][3]));
#pragma unroll
            for (int off = 8; off; off >>= 1)
                lm = fmaxf(lm, __shfl_xor_sync(0xffffffffu, lm, off, 16));
            float newm = fmaxf(m_i[i], lm);
            float corr = __expf(m_i[i] - newm);
            float pr[4];
            float rs = 0.f;
#pragma unroll
            for (int j = 0; j < 4; j++) {
                pr[j] = __expf(s[i][j] - newm);
                rs += pr[j];
            }
#pragma unroll
            for (int off = 8; off; off >>= 1)
                rs += __shfl_xor_sync(0xffffffffu, rs, off, 16);
            l_i[i] = l_i[i] * corr + rs;
            m_i[i] = newm;
#pragma unroll
            for (int j = 0; j < 4; j++) o[i][j] *= corr;
            *(float4*)&Ps[(ty * 4 + i) * 68 + tx * 4] =
                make_float4(pr[0], pr[1], pr[2], pr[3]);
        }
        __syncthreads();

#pragma unroll 2
        for (int n4 = 0; n4 < 64; n4 += 4) {
            float pv[4][4];
#pragma unroll
            for (int i = 0; i < 4; i++)
                *(float4*)pv[i] = *(const float4*)&Ps[(ty * 4 + i) * 68 + n4];
#pragma unroll
            for (int t = 0; t < 4; t++) {
                float vv[4];
                *(float4*)vv = *(const float4*)&Vs[(n4 + t) * 64 + tx * 4];
#pragma unroll
                for (int i = 0; i < 4; i++)
#pragma unroll
                    for (int j = 0; j < 4; j++) o[i][j] += pv[i][t] * vv[j];
            }
        }
    }

#pragma unroll
    for (int i = 0; i < 4; i++) {
        float inv = 1.0f / l_i[i];
        float4 r = make_float4(o[i][0] * inv, o[i][1] * inv,
                               o[i][2] * inv, o[i][3] * inv);
        *(float4*)(Og + base + (size_t)(q0 + ty * 4 + i) * DMODEL + tx * 4) = r;
    }
}

// ========================================================================
extern "C" void kernel_launch(void* const* d_in, const int* in_sizes, int n_in,
                              void* d_out, int out_size) {
    (void)in_sizes; (void)n_in; (void)out_size;
    const float* x  = (const float*)d_in[0];
    const float* Wq = (const float*)d_in[1];
    const float* Wk = (const float*)d_in[2];
    const float* Wv = (const float*)d_in[3];
    const float* Wo = (const float*)d_in[4];
    float* out = (float*)d_out;

    float *q, *k, *v, *att;
    cudaGetSymbolAddress((void**)&q,   g_q);
    cudaGetSymbolAddress((void**)&k,   g_k);
    cudaGetSymbolAddress((void**)&v,   g_v);
    cudaGetSymbolAddress((void**)&att, g_att);

    dim3 gg(DMODEL / 128, MTOT / 128);   // (8, 32)
    sgemm_tc<<<gg, 256>>>(x, Wq, q);
    sgemm_tc<<<gg, 256>>>(x, Wk, k);
    sgemm_tc<<<gg, 256>>>(x, Wv, v);

    rope_table_kernel<<<(S_LEN * (DK / 2) + 255) / 256, 256>>>();
    rope_apply_kernel<<<(BATCH * S_LEN * (DMODEL / 2) + 255) / 256, 256>>>(q);
    rope_apply_kernel<<<(BATCH * S_LEN * (DMODEL / 2) + 255) / 256, 256>>>(k);

    cudaFuncSetAttribute(flash_attn,
                         cudaFuncAttributeMaxDynamicSharedMemorySize, 66560);
    flash_attn<<<dim3(S_LEN / 64, NHEADS, BATCH), 256, 66560>>>(q, k, v, att);

    sgemm_tc<<<gg, 256>>>(att, Wo, out);
}

// round 8
// speedup vs baseline: 2.1754x; 2.1314x over previous
#include <cuda_runtime.h>
#include <cuda_bf16.h>
#include <math.h>
#include <cstdint>

#define S_LEN  2048
#define BATCH  2
#define DMODEL 1024
#define NHEADS 16
#define DK     64
#define MTOT   (BATCH * S_LEN)   // 4096

// ---------------- scratch (static device allocations; no cudaMalloc) -----
__device__ float  g_q[(size_t)BATCH * S_LEN * DMODEL];
__device__ float  g_k[(size_t)BATCH * S_LEN * DMODEL];
__device__ float  g_v[(size_t)BATCH * S_LEN * DMODEL];
__device__ float  g_att[(size_t)BATCH * S_LEN * DMODEL];
__device__ float2 g_rope[S_LEN * (DK / 2)];

__device__ __nv_bfloat16 g_xh[(size_t)MTOT * DMODEL];
__device__ __nv_bfloat16 g_xl[(size_t)MTOT * DMODEL];
__device__ __nv_bfloat16 g_ah[(size_t)MTOT * DMODEL];
__device__ __nv_bfloat16 g_al[(size_t)MTOT * DMODEL];
__device__ __nv_bfloat16 g_wh[4][(size_t)DMODEL * DMODEL];
__device__ __nv_bfloat16 g_wl[4][(size_t)DMODEL * DMODEL];

// ---------------- mma / ldmatrix helpers ---------------------------------
__device__ __forceinline__ uint32_t smem_u32(const void* p) {
    uint32_t a;
    asm("{ .reg .u64 t; cvta.to.shared.u64 t, %1; cvt.u32.u64 %0, t; }"
        : "=r"(a) : "l"(p));
    return a;
}
__device__ __forceinline__ void ldmat4(uint32_t* r, uint32_t addr) {
    asm volatile("ldmatrix.sync.aligned.m8n8.x4.shared.b16 {%0,%1,%2,%3}, [%4];"
                 : "=r"(r[0]), "=r"(r[1]), "=r"(r[2]), "=r"(r[3]) : "r"(addr));
}
__device__ __forceinline__ void mma_bf16(float* d, const uint32_t* a,
                                         const uint32_t* b) {
    asm volatile(
        "mma.sync.aligned.m16n8k16.row.col.f32.bf16.bf16.f32 "
        "{%0,%1,%2,%3}, {%4,%5,%6,%7}, {%8,%9}, {%0,%1,%2,%3};"
        : "+f"(d[0]), "+f"(d[1]), "+f"(d[2]), "+f"(d[3])
        : "r"(a[0]), "r"(a[1]), "r"(a[2]), "r"(a[3]), "r"(b[0]), "r"(b[1]));
}

// ========================================================================
// split: fp32 -> bf16 hi + bf16 lo  (a ~= hi + lo, residual ~2^-16 rel)
// ========================================================================
__global__ void split_kernel(const float* __restrict__ src,
                             __nv_bfloat16* __restrict__ hi,
                             __nv_bfloat16* __restrict__ lo, int n4) {
    int i = blockIdx.x * blockDim.x + threadIdx.x;
    if (i >= n4) return;
    float4 v = ((const float4*)src)[i];
    __nv_bfloat16 h[4], l[4];
    float f[4] = {v.x, v.y, v.z, v.w};
#pragma unroll
    for (int j = 0; j < 4; j++) {
        h[j] = __float2bfloat16_rn(f[j]);
        l[j] = __float2bfloat16_rn(f[j] - __bfloat162float(h[j]));
    }
    ((uint2*)hi)[i] = *(uint2*)h;
    ((uint2*)lo)[i] = *(uint2*)l;
}

// ========================================================================
// bf16 HMMA GEMM:  C[m,n] = sum_k A[m,k]*B[n,k]  via 3-term hi/lo.
// BM=BN=128, BK=32, 256 thr (8 warps 2x4), warp tile 64x32, mma m16n8k16.
// Smem tiles padded to stride 40 bf16 (80B) -> conflict-free ldmatrix.
// blockIdx.z selects among up to 3 (B, C) pairs (fused QKV).
// ========================================================================
#define LDA 40            // bf16 elements per smem row (80 bytes)
#define TILE_SM (128 * LDA)   // bf16 elems per tile

struct GemmArgs {
    const __nv_bfloat16 *Ah, *Al;
    const __nv_bfloat16 *Bh[3], *Bl[3];
    float* C[3];
};

__global__ __launch_bounds__(256) void gemm_hmma(GemmArgs args) {
    __shared__ __nv_bfloat16 sAh[TILE_SM], sAl[TILE_SM];
    __shared__ __nv_bfloat16 sBh[TILE_SM], sBl[TILE_SM];

    const int z    = blockIdx.z;
    const __nv_bfloat16* Ahg = args.Ah;
    const __nv_bfloat16* Alg = args.Al;
    const __nv_bfloat16* Bhg = args.Bh[z];
    const __nv_bfloat16* Blg = args.Bl[z];
    float* C = args.C[z];

    const int tid  = threadIdx.x;
    const int lane = tid & 31;
    const int wid  = tid >> 5;
    const int wm   = wid >> 2;          // 0..1  (64 rows each)
    const int wn   = wid & 3;           // 0..3  (32 cols each)
    const int bm   = blockIdx.y * 128;
    const int bn   = blockIdx.x * 128;

    const uint32_t sAh_b = smem_u32(sAh);
    const uint32_t sAl_b = smem_u32(sAl);
    const uint32_t sBh_b = smem_u32(sBh);
    const uint32_t sBl_b = smem_u32(sBl);

    // lane-dependent ldmatrix byte offsets (within a tile)
    const int l7  = lane & 7;
    const int l8  = (lane >> 3) & 1;
    const int l16 = lane >> 4;
    const uint32_t aoff = (uint32_t)((wm * 64 + l7 + l8 * 8) * 80 + l16 * 16);
    const uint32_t boff = (uint32_t)((wn * 32 + l16 * 8 + l7) * 80 + l8 * 16);

    float acc[4][4][4];
#pragma unroll
    for (int mt = 0; mt < 4; mt++)
#pragma unroll
        for (int nt = 0; nt < 4; nt++)
#pragma unroll
            for (int e = 0; e < 4; e++) acc[mt][nt][e] = 0.f;

    // gmem chunk indexing: f in 0..511 (16B units), r=f>>2 row, cg=f&3
    const int r0 = (tid + 0)   >> 2, cg0 = (tid + 0)   & 3;
    const int r1 = (tid + 256) >> 2, cg1 = (tid + 256) & 3;

    uint4 pah[2], pal[2], pbh[2], pbl[2];
    {
        const size_t ga0 = (size_t)(bm + r0) * DMODEL + cg0 * 8;
        const size_t ga1 = (size_t)(bm + r1) * DMODEL + cg1 * 8;
        const size_t gb0 = (size_t)(bn + r0) * DMODEL + cg0 * 8;
        const size_t gb1 = (size_t)(bn + r1) * DMODEL + cg1 * 8;
        pah[0] = *(const uint4*)(Ahg + ga0); pah[1] = *(const uint4*)(Ahg + ga1);
        pal[0] = *(const uint4*)(Alg + ga0); pal[1] = *(const uint4*)(Alg + ga1);
        pbh[0] = *(const uint4*)(Bhg + gb0); pbh[1] = *(const uint4*)(Bhg + gb1);
        pbl[0] = *(const uint4*)(Blg + gb0); pbl[1] = *(const uint4*)(Blg + gb1);
    }
    const uint32_t so0 = (uint32_t)(r0 * 80 + cg0 * 16);
    const uint32_t so1 = (uint32_t)(r1 * 80 + cg1 * 16);

    *(uint4*)((char*)sAh + so0) = pah[0]; *(uint4*)((char*)sAh + so1) = pah[1];
    *(uint4*)((char*)sAl + so0) = pal[0]; *(uint4*)((char*)sAl + so1) = pal[1];
    *(uint4*)((char*)sBh + so0) = pbh[0]; *(uint4*)((char*)sBh + so1) = pbh[1];
    *(uint4*)((char*)sBl + so0) = pbl[0]; *(uint4*)((char*)sBl + so1) = pbl[1];
    __syncthreads();

    for (int kk = 0; kk < DMODEL; kk += 32) {
        const bool more = (kk + 32 < DMODEL);
        if (more) {
            const int kn = kk + 32;
            const size_t ga0 = (size_t)(bm + r0) * DMODEL + kn + cg0 * 8;
            const size_t ga1 = (size_t)(bm + r1) * DMODEL + kn + cg1 * 8;
            const size_t gb0 = (size_t)(bn + r0) * DMODEL + kn + cg0 * 8;
            const size_t gb1 = (size_t)(bn + r1) * DMODEL + kn + cg1 * 8;
            pah[0] = *(const uint4*)(Ahg + ga0); pah[1] = *(const uint4*)(Ahg + ga1);
            pal[0] = *(const uint4*)(Alg + ga0); pal[1] = *(const uint4*)(Alg + ga1);
            pbh[0] = *(const uint4*)(Bhg + gb0); pbh[1] = *(const uint4*)(Bhg + gb1);
            pbl[0] = *(const uint4*)(Blg + gb0); pbl[1] = *(const uint4*)(Blg + gb1);
        }

#pragma unroll
        for (int ks = 0; ks < 2; ks++) {
            const uint32_t kso = ks * 32;   // 16 bf16 = 32 bytes along k
            uint32_t Ah[4][4], Al[4][4], Bh[4][2], Bl[4][2];
#pragma unroll
            for (int mt = 0; mt < 4; mt++) {
                const uint32_t ao = aoff + mt * (16 * 80) + kso;
                ldmat4(Ah[mt], sAh_b + ao);
                ldmat4(Al[mt], sAl_b + ao);
            }
#pragma unroll
            for (int np = 0; np < 2; np++) {
                const uint32_t bo = boff + np * (16 * 80) + kso;
                uint32_t t[4];
                ldmat4(t, sBh_b + bo);
                Bh[np * 2][0] = t[0]; Bh[np * 2][1] = t[1];
                Bh[np * 2 + 1][0] = t[2]; Bh[np * 2 + 1][1] = t[3];
                ldmat4(t, sBl_b + bo);
                Bl[np * 2][0] = t[0]; Bl[np * 2][1] = t[1];
                Bl[np * 2 + 1][0] = t[2]; Bl[np * 2 + 1][1] = t[3];
            }
#pragma unroll
            for (int mt = 0; mt < 4; mt++)
#pragma unroll
                for (int nt = 0; nt < 4; nt++) {
                    mma_bf16(acc[mt][nt], Ah[mt], Bh[nt]);
                    mma_bf16(acc[mt][nt], Ah[mt], Bl[nt]);
                    mma_bf16(acc[mt][nt], Al[mt], Bh[nt]);
                }
        }

        if (more) {
            __syncthreads();
            *(uint4*)((char*)sAh + so0) = pah[0]; *(uint4*)((char*)sAh + so1) = pah[1];
            *(uint4*)((char*)sAl + so0) = pal[0]; *(uint4*)((char*)sAl + so1) = pal[1];
            *(uint4*)((char*)sBh + so0) = pbh[0]; *(uint4*)((char*)sBh + so1) = pbh[1];
            *(uint4*)((char*)sBl + so0) = pbl[0]; *(uint4*)((char*)sBl + so1) = pbl[1];
            __syncthreads();
        }
    }

    // epilogue: mma fragment layout (g=lane>>2 row, tig=lane&3 col pair)
    const int g   = lane >> 2;
    const int tig = lane & 3;
#pragma unroll
    for (int mt = 0; mt < 4; mt++) {
        const int row = bm + wm * 64 + mt * 16 + g;
#pragma unroll
        for (int nt = 0; nt < 4; nt++) {
            const int col = bn + wn * 32 + nt * 8 + tig * 2;
            *(float2*)(C + (size_t)row * DMODEL + col) =
                make_float2(acc[mt][nt][0], acc[mt][nt][1]);
            *(float2*)(C + (size_t)(row + 8) * DMODEL + col) =
                make_float2(acc[mt][nt][2], acc[mt][nt][3]);
        }
    }
}

// ========================================================================
// RoPE (unchanged, proven)
// ========================================================================
__global__ void rope_table_kernel() {
    int idx = blockIdx.x * blockDim.x + threadIdx.x;
    if (idx >= S_LEN * (DK / 2)) return;
    int s = idx >> 5;
    int i = idx & 31;
    float freq = 1.0f / powf(10000.0f, (float)(2 * i) / 64.0f);
    float ang  = (float)s * freq;
    double a   = (double)ang;
    g_rope[idx] = make_float2((float)cos(a), (float)sin(a));
}

__global__ void rope_apply_kernel(float* __restrict__ t) {
    int idx = blockIdx.x * blockDim.x + threadIdx.x;
    if (idx >= BATCH * S_LEN * (DMODEL / 2)) return;
    int row = idx >> 9;
    int pp  = idx & 511;
    int s   = row & (S_LEN - 1);
    float2 cs = g_rope[(s << 5) + (pp & 31)];
    float2 v  = ((const float2*)t)[idx];
    float2 r;
    r.x = v.x * cs.x - v.y * cs.y;
    r.y = v.x * cs.y + v.y * cs.x;
    ((float2*)t)[idx] = r;
}

// ========================================================================
// Flash attention, fp32 scalar (round-1 proven version).
// ========================================================================
__global__ __launch_bounds__(256) void flash_attn(const float* __restrict__ Qg,
                                                  const float* __restrict__ Kg,
                                                  const float* __restrict__ Vg,
                                                  float* __restrict__ Og) {
    extern __shared__ float sm[];
    float* Qt = sm;
    float* Kt = sm + 4096;
    float* Vs = sm + 8192;
    float* Ps = sm + 12288;

    const int qt  = gridDim.x - 1 - blockIdx.x;
    const int h   = blockIdx.y;
    const int b   = blockIdx.z;
    const int tid = threadIdx.x;
    const int tx  = tid & 15;
    const int ty  = tid >> 4;
    const size_t base = ((size_t)b * S_LEN) * DMODEL + h * DK;
    const int q0 = qt * 64;

#pragma unroll
    for (int p = 0; p < 4; p++) {
        int f = tid + p * 256;
        int m = f & 63, kg = f >> 6;
        float4 v = *(const float4*)(Qg + base + (size_t)(q0 + m) * DMODEL + kg * 4);
        Qt[(kg * 4 + 0) * 64 + m] = v.x;
        Qt[(kg * 4 + 1) * 64 + m] = v.y;
        Qt[(kg * 4 + 2) * 64 + m] = v.z;
        Qt[(kg * 4 + 3) * 64 + m] = v.w;
    }

    float o[4][4];
    float m_i[4], l_i[4];
#pragma unroll
    for (int i = 0; i < 4; i++) {
        m_i[i] = -INFINITY;
        l_i[i] = 0.f;
#pragma unroll
        for (int j = 0; j < 4; j++) o[i][j] = 0.f;
    }
    const float scale = 0.125f;

    for (int kt = 0; kt <= qt; kt++) {
        const int k0 = kt * 64;
        __syncthreads();
#pragma unroll
        for (int p = 0; p < 4; p++) {
            int f = tid + p * 256;
            int n = f & 63, kg = f >> 6;
            float4 kv = *(const float4*)(Kg + base + (size_t)(k0 + n) * DMODEL + kg * 4);
            Kt[(kg * 4 + 0) * 64 + n] = kv.x;
            Kt[(kg * 4 + 1) * 64 + n] = kv.y;
            Kt[(kg * 4 + 2) * 64 + n] = kv.z;
            Kt[(kg * 4 + 3) * 64 + n] = kv.w;
            int n2 = f >> 4, cc = (f & 15) * 4;
            *(float4*)&Vs[n2 * 64 + cc] =
                *(const float4*)(Vg + base + (size_t)(k0 + n2) * DMODEL + cc);
        }
        __syncthreads();

        float s[4][4];
#pragma unroll
        for (int i = 0; i < 4; i++)
#pragma unroll
            for (int j = 0; j < 4; j++) s[i][j] = 0.f;

#pragma unroll 4
        for (int d = 0; d < 64; d++) {
            float qa[4], kb[4];
            *(float4*)qa = *(const float4*)&Qt[d * 64 + ty * 4];
            *(float4*)kb = *(const float4*)&Kt[d * 64 + tx * 4];
#pragma unroll
            for (int i = 0; i < 4; i++)
#pragma unroll
                for (int j = 0; j < 4; j++) s[i][j] += qa[i] * kb[j];
        }

        const bool diag = (kt == qt);
#pragma unroll
        for (int i = 0; i < 4; i++) {
#pragma unroll
            for (int j = 0; j < 4; j++) {
                s[i][j] *= scale;
                if (diag && (k0 + tx * 4 + j > q0 + ty * 4 + i)) s[i][j] = -INFINITY;
            }
            float lm = fmaxf(fmaxf(s[i][0], s[i][1]), fmaxf(s[i][2], s[i][3]));
#pragma unroll
            for (int off = 8; off; off >>= 1)
                lm = fmaxf(lm, __shfl_xor_sync(0xffffffffu, lm, off, 16));
            float newm = fmaxf(m_i[i], lm);
            float corr = __expf(m_i[i] - newm);
            float pr[4];
            float rs = 0.f;
#pragma unroll
            for (int j = 0; j < 4; j++) {
                pr[j] = __expf(s[i][j] - newm);
                rs += pr[j];
            }
#pragma unroll
            for (int off = 8; off; off >>= 1)
                rs += __shfl_xor_sync(0xffffffffu, rs, off, 16);
            l_i[i] = l_i[i] * corr + rs;
            m_i[i] = newm;
#pragma unroll
            for (int j = 0; j < 4; j++) o[i][j] *= corr;
            *(float4*)&Ps[(ty * 4 + i) * 68 + tx * 4] =
                make_float4(pr[0], pr[1], pr[2], pr[3]);
        }
        __syncthreads();

#pragma unroll 2
        for (int n4 = 0; n4 < 64; n4 += 4) {
            float pv[4][4];
#pragma unroll
            for (int i = 0; i < 4; i++)
                *(float4*)pv[i] = *(const float4*)&Ps[(ty * 4 + i) * 68 + n4];
#pragma unroll
            for (int t = 0; t < 4; t++) {
                float vv[4];
                *(float4*)vv = *(const float4*)&Vs[(n4 + t) * 64 + tx * 4];
#pragma unroll
                for (int i = 0; i < 4; i++)
#pragma unroll
                    for (int j = 0; j < 4; j++) o[i][j] += pv[i][t] * vv[j];
            }
        }
    }

#pragma unroll
    for (int i = 0; i < 4; i++) {
        float inv = 1.0f / l_i[i];
        float4 r = make_float4(o[i][0] * inv, o[i][1] * inv,
                               o[i][2] * inv, o[i][3] * inv);
        *(float4*)(Og + base + (size_t)(q0 + ty * 4 + i) * DMODEL + tx * 4) = r;
    }
}

// ========================================================================
extern "C" void kernel_launch(void* const* d_in, const int* in_sizes, int n_in,
                              void* d_out, int out_size) {
    (void)in_sizes; (void)n_in; (void)out_size;
    const float* x  = (const float*)d_in[0];
    const float* W[4] = {(const float*)d_in[1], (const float*)d_in[2],
                         (const float*)d_in[3], (const float*)d_in[4]};
    float* out = (float*)d_out;

    float *q, *k, *v, *att;
    cudaGetSymbolAddress((void**)&q,   g_q);
    cudaGetSymbolAddress((void**)&k,   g_k);
    cudaGetSymbolAddress((void**)&v,   g_v);
    cudaGetSymbolAddress((void**)&att, g_att);
    __nv_bfloat16 *xh, *xl, *ah, *al, *wh, *wl;
    cudaGetSymbolAddress((void**)&xh, g_xh);
    cudaGetSymbolAddress((void**)&xl, g_xl);
    cudaGetSymbolAddress((void**)&ah, g_ah);
    cudaGetSymbolAddress((void**)&al, g_al);
    cudaGetSymbolAddress((void**)&wh, g_wh);
    cudaGetSymbolAddress((void**)&wl, g_wl);

    const int NX4 = MTOT * DMODEL / 4;      // 1M float4
    const int NW4 = DMODEL * DMODEL / 4;    // 256K float4
    split_kernel<<<NX4 / 256, 256>>>(x, xh, xl, NX4);
    for (int i = 0; i < 4; i++)
        split_kernel<<<NW4 / 256, 256>>>(W[i], wh + (size_t)i * DMODEL * DMODEL,
                                         wl + (size_t)i * DMODEL * DMODEL, NW4);

    // fused QKV projection (grid.z = 3)
    GemmArgs qkv;
    qkv.Ah = xh; qkv.Al = xl;
    for (int i = 0; i < 3; i++) {
        qkv.Bh[i] = wh + (size_t)i * DMODEL * DMODEL;
        qkv.Bl[i] = wl + (size_t)i * DMODEL * DMODEL;
    }
    qkv.C[0] = q; qkv.C[1] = k; qkv.C[2] = v;
    dim3 gq(DMODEL / 128, MTOT / 128, 3);
    gemm_hmma<<<gq, 256>>>(qkv);

    rope_table_kernel<<<(S_LEN * (DK / 2) + 255) / 256, 256>>>();
    rope_apply_kernel<<<(BATCH * S_LEN * (DMODEL / 2) + 255) / 256, 256>>>(q);
    rope_apply_kernel<<<(BATCH * S_LEN * (DMODEL / 2) + 255) / 256, 256>>>(k);

    cudaFuncSetAttribute(flash_attn,
                         cudaFuncAttributeMaxDynamicSharedMemorySize, 66560);
    flash_attn<<<dim3(S_LEN / 64, NHEADS, BATCH), 256, 66560>>>(q, k, v, att);

    split_kernel<<<NX4 / 256, 256>>>(att, ah, al, NX4);
    GemmArgs op;
    op.Ah = ah; op.Al = al;
    op.Bh[0] = wh + 3 * (size_t)DMODEL * DMODEL;
    op.Bl[0] = wl + 3 * (size_t)DMODEL * DMODEL;
    op.C[0] = out;
    dim3 go(DMODEL / 128, MTOT / 128, 1);
    gemm_hmma<<<go, 256>>>(op);
}

// round 12
// speedup vs baseline: 4.0131x; 1.8447x over previous
#include <cuda_runtime.h>
#include <cuda_bf16.h>
#include <math.h>
#include <cstdint>

#define S_LEN  2048
#define BATCH  2
#define DMODEL 1024
#define NHEADS 16
#define DK     64
#define MTOT   (BATCH * S_LEN)   // 4096

// ---------------- scratch (static device allocations; no cudaMalloc) -----
__device__ float2 g_rope[S_LEN * (DK / 2)];
__device__ __nv_bfloat16 g_xh[(size_t)MTOT * DMODEL];
__device__ __nv_bfloat16 g_xl[(size_t)MTOT * DMODEL];
__device__ __nv_bfloat16 g_qh[(size_t)MTOT * DMODEL];
__device__ __nv_bfloat16 g_ql[(size_t)MTOT * DMODEL];
__device__ __nv_bfloat16 g_kh[(size_t)MTOT * DMODEL];
__device__ __nv_bfloat16 g_kl[(size_t)MTOT * DMODEL];
__device__ __nv_bfloat16 g_vh[(size_t)MTOT * DMODEL];
__device__ __nv_bfloat16 g_vl[(size_t)MTOT * DMODEL];
__device__ __nv_bfloat16 g_oh[(size_t)MTOT * DMODEL];
__device__ __nv_bfloat16 g_ol[(size_t)MTOT * DMODEL];
__device__ __nv_bfloat16 g_wh[4][(size_t)DMODEL * DMODEL];
__device__ __nv_bfloat16 g_wl[4][(size_t)DMODEL * DMODEL];

// ---------------- mma / ldmatrix helpers ---------------------------------
__device__ __forceinline__ uint32_t smem_u32(const void* p) {
    uint32_t a;
    asm("{ .reg .u64 t; cvta.to.shared.u64 t, %1; cvt.u32.u64 %0, t; }"
        : "=r"(a) : "l"(p));
    return a;
}
__device__ __forceinline__ void ldmat4(uint32_t* r, uint32_t addr) {
    asm volatile("ldmatrix.sync.aligned.m8n8.x4.shared.b16 {%0,%1,%2,%3}, [%4];"
                 : "=r"(r[0]), "=r"(r[1]), "=r"(r[2]), "=r"(r[3]) : "r"(addr));
}
__device__ __forceinline__ void ldmat4t(uint32_t* r, uint32_t addr) {
    asm volatile("ldmatrix.sync.aligned.m8n8.x4.trans.shared.b16 {%0,%1,%2,%3}, [%4];"
                 : "=r"(r[0]), "=r"(r[1]), "=r"(r[2]), "=r"(r[3]) : "r"(addr));
}
__device__ __forceinline__ void mma_bf16(float* d, const uint32_t* a,
                                         const uint32_t* b) {
    asm volatile(
        "mma.sync.aligned.m16n8k16.row.col.f32.bf16.bf16.f32 "
        "{%0,%1,%2,%3}, {%4,%5,%6,%7}, {%8,%9}, {%0,%1,%2,%3};"
        : "+f"(d[0]), "+f"(d[1]), "+f"(d[2]), "+f"(d[3])
        : "r"(a[0]), "r"(a[1]), "r"(a[2]), "r"(a[3]), "r"(b[0]), "r"(b[1]));
}
// pack two bf16 (lo = first arg) into one u32
__device__ __forceinline__ uint32_t pack_bf16(__nv_bfloat16 lo, __nv_bfloat16 hi) {
    __nv_bfloat162 t(lo, hi);
    return *(uint32_t*)&t;
}
__device__ __forceinline__ uint32_t pack_bf16f(float lo, float hi) {
    uint32_t r;
    asm("cvt.rn.bf16x2.f32 %0, %1, %2;" : "=r"(r) : "f"(hi), "f"(lo));
    return r;
}

// ========================================================================
// split: fp32 -> bf16 hi + bf16 lo
// ========================================================================
__global__ void split_kernel(const float* __restrict__ src,
                             __nv_bfloat16* __restrict__ hi,
                             __nv_bfloat16* __restrict__ lo, int n4) {
    int i = blockIdx.x * blockDim.x + threadIdx.x;
    if (i >= n4) return;
    float4 v = ((const float4*)src)[i];
    __nv_bfloat16 h[4], l[4];
    float f[4] = {v.x, v.y, v.z, v.w};
#pragma unroll
    for (int j = 0; j < 4; j++) {
        h[j] = __float2bfloat16_rn(f[j]);
        l[j] = __float2bfloat16_rn(f[j] - __bfloat162float(h[j]));
    }
    ((uint2*)hi)[i] = *(uint2*)h;
    ((uint2*)lo)[i] = *(uint2*)l;
}

// ========================================================================
// RoPE table
// ========================================================================
__global__ void rope_table_kernel() {
    int idx = blockIdx.x * blockDim.x + threadIdx.x;
    if (idx >= S_LEN * (DK / 2)) return;
    int s = idx >> 5;
    int i = idx & 31;
    float freq = 1.0f / powf(10000.0f, (float)(2 * i) / 64.0f);
    float ang  = (float)s * freq;
    double a   = (double)ang;
    g_rope[idx] = make_float2((float)cos(a), (float)sin(a));
}

// ========================================================================
// bf16 HMMA GEMM (validated core).  Epilogue modes:
//   0 = fp32 store, 1 = rope + bf16 hi/lo split, 2 = bf16 hi/lo split
// ========================================================================
struct GemmArgs {
    const __nv_bfloat16 *Ah, *Al;
    const __nv_bfloat16 *Bh[3], *Bl[3];
    float* Cf[3];
    __nv_bfloat16 *Ch[3], *Cl[3];
    int mode[3];
};

__global__ __launch_bounds__(256) void gemm_hmma(GemmArgs args) {
    __shared__ __nv_bfloat16 sAh[128 * 40], sAl[128 * 40];
    __shared__ __nv_bfloat16 sBh[128 * 40], sBl[128 * 40];

    const int z = blockIdx.z;
    const __nv_bfloat16* Ahg = args.Ah;
    const __nv_bfloat16* Alg = args.Al;
    const __nv_bfloat16* Bhg = args.Bh[z];
    const __nv_bfloat16* Blg = args.Bl[z];
    const int mode = args.mode[z];

    const int tid  = threadIdx.x;
    const int lane = tid & 31;
    const int wid  = tid >> 5;
    const int wm   = wid >> 2;
    const int wn   = wid & 3;
    const int bm   = blockIdx.y * 128;
    const int bn   = blockIdx.x * 128;

    const uint32_t sAh_b = smem_u32(sAh);
    const uint32_t sAl_b = smem_u32(sAl);
    const uint32_t sBh_b = smem_u32(sBh);
    const uint32_t sBl_b = smem_u32(sBl);

    const int l7  = lane & 7;
    const int l8  = (lane >> 3) & 1;
    const int l16 = lane >> 4;
    const uint32_t aoff = (uint32_t)((wm * 64 + l7 + l8 * 8) * 80 + l16 * 16);
    const uint32_t boff = (uint32_t)((wn * 32 + l16 * 8 + l7) * 80 + l8 * 16);

    float acc[4][4][4];
#pragma unroll
    for (int mt = 0; mt < 4; mt++)
#pragma unroll
        for (int nt = 0; nt < 4; nt++)
#pragma unroll
            for (int e = 0; e < 4; e++) acc[mt][nt][e] = 0.f;

    const int r0 = (tid + 0)   >> 2, cg0 = (tid + 0)   & 3;
    const int r1 = (tid + 256) >> 2, cg1 = (tid + 256) & 3;

    uint4 pah[2], pal[2], pbh[2], pbl[2];
    {
        const size_t ga0 = (size_t)(bm + r0) * DMODEL + cg0 * 8;
        const size_t ga1 = (size_t)(bm + r1) * DMODEL + cg1 * 8;
        const size_t gb0 = (size_t)(bn + r0) * DMODEL + cg0 * 8;
        const size_t gb1 = (size_t)(bn + r1) * DMODEL + cg1 * 8;
        pah[0] = *(const uint4*)(Ahg + ga0); pah[1] = *(const uint4*)(Ahg + ga1);
        pal[0] = *(const uint4*)(Alg + ga0); pal[1] = *(const uint4*)(Alg + ga1);
        pbh[0] = *(const uint4*)(Bhg + gb0); pbh[1] = *(const uint4*)(Bhg + gb1);
        pbl[0] = *(const uint4*)(Blg + gb0); pbl[1] = *(const uint4*)(Blg + gb1);
    }
    const uint32_t so0 = (uint32_t)(r0 * 80 + cg0 * 16);
    const uint32_t so1 = (uint32_t)(r1 * 80 + cg1 * 16);

    *(uint4*)((char*)sAh + so0) = pah[0]; *(uint4*)((char*)sAh + so1) = pah[1];
    *(uint4*)((char*)sAl + so0) = pal[0]; *(uint4*)((char*)sAl + so1) = pal[1];
    *(uint4*)((char*)sBh + so0) = pbh[0]; *(uint4*)((char*)sBh + so1) = pbh[1];
    *(uint4*)((char*)sBl + so0) = pbl[0]; *(uint4*)((char*)sBl + so1) = pbl[1];
    __syncthreads();

    for (int kk = 0; kk < DMODEL; kk += 32) {
        const bool more = (kk + 32 < DMODEL);
        if (more) {
            const int kn = kk + 32;
            const size_t ga0 = (size_t)(bm + r0) * DMODEL + kn + cg0 * 8;
            const size_t ga1 = (size_t)(bm + r1) * DMODEL + kn + cg1 * 8;
            const size_t gb0 = (size_t)(bn + r0) * DMODEL + kn + cg0 * 8;
            const size_t gb1 = (size_t)(bn + r1) * DMODEL + kn + cg1 * 8;
            pah[0] = *(const uint4*)(Ahg + ga0); pah[1] = *(const uint4*)(Ahg + ga1);
            pal[0] = *(const uint4*)(Alg + ga0); pal[1] = *(const uint4*)(Alg + ga1);
            pbh[0] = *(const uint4*)(Bhg + gb0); pbh[1] = *(const uint4*)(Bhg + gb1);
            pbl[0] = *(const uint4*)(Blg + gb0); pbl[1] = *(const uint4*)(Blg + gb1);
        }

#pragma unroll
        for (int ks = 0; ks < 2; ks++) {
            const uint32_t kso = ks * 32;
            uint32_t Ahf[4][4], Alf[4][4], Bhf[4][2], Blf[4][2];
#pragma unroll
            for (int mt = 0; mt < 4; mt++) {
                const uint32_t ao = aoff + mt * (16 * 80) + kso;
                ldmat4(Ahf[mt], sAh_b + ao);
                ldmat4(Alf[mt], sAl_b + ao);
            }
#pragma unroll
            for (int np = 0; np < 2; np++) {
                const uint32_t bo = boff + np * (16 * 80) + kso;
                uint32_t t[4];
                ldmat4(t, sBh_b + bo);
                Bhf[np * 2][0] = t[0]; Bhf[np * 2][1] = t[1];
                Bhf[np * 2 + 1][0] = t[2]; Bhf[np * 2 + 1][1] = t[3];
                ldmat4(t, sBl_b + bo);
                Blf[np * 2][0] = t[0]; Blf[np * 2][1] = t[1];
                Blf[np * 2 + 1][0] = t[2]; Blf[np * 2 + 1][1] = t[3];
            }
#pragma unroll
            for (int mt = 0; mt < 4; mt++)
#pragma unroll
                for (int nt = 0; nt < 4; nt++) {
                    mma_bf16(acc[mt][nt], Ahf[mt], Bhf[nt]);
                    mma_bf16(acc[mt][nt], Ahf[mt], Blf[nt]);
                    mma_bf16(acc[mt][nt], Alf[mt], Bhf[nt]);
                }
        }

        if (more) {
            __syncthreads();
            *(uint4*)((char*)sAh + so0) = pah[0]; *(uint4*)((char*)sAh + so1) = pah[1];
            *(uint4*)((char*)sAl + so0) = pal[0]; *(uint4*)((char*)sAl + so1) = pal[1];
            *(uint4*)((char*)sBh + so0) = pbh[0]; *(uint4*)((char*)sBh + so1) = pbh[1];
            *(uint4*)((char*)sBl + so0) = pbl[0]; *(uint4*)((char*)sBl + so1) = pbl[1];
            __syncthreads();
        }
    }

    const int g   = lane >> 2;
    const int tig = lane & 3;
#pragma unroll
    for (int mt = 0; mt < 4; mt++) {
        const int row = bm + wm * 64 + mt * 16 + g;
#pragma unroll
        for (int nt = 0; nt < 4; nt++) {
            const int col = bn + wn * 32 + nt * 8 + tig * 2;
            float e0 = acc[mt][nt][0], o0 = acc[mt][nt][1];
            float e1 = acc[mt][nt][2], o1 = acc[mt][nt][3];
            if (mode == 0) {
                *(float2*)(args.Cf[z] + (size_t)row * DMODEL + col) =
                    make_float2(e0, o0);
                *(float2*)(args.Cf[z] + (size_t)(row + 8) * DMODEL + col) =
                    make_float2(e1, o1);
            } else {
                if (mode == 1) {
                    const int i = (col & 63) >> 1;
                    float2 c0 = g_rope[((row & (S_LEN - 1)) << 5) + i];
                    float2 c1 = g_rope[(((row + 8) & (S_LEN - 1)) << 5) + i];
                    float te = e0 * c0.x - o0 * c0.y;
                    o0 = e0 * c0.y + o0 * c0.x; e0 = te;
                    te = e1 * c1.x - o1 * c1.y;
                    o1 = e1 * c1.y + o1 * c1.x; e1 = te;
                }
                __nv_bfloat16 he0 = __float2bfloat16_rn(e0);
                __nv_bfloat16 ho0 = __float2bfloat16_rn(o0);
                __nv_bfloat16 he1 = __float2bfloat16_rn(e1);
                __nv_bfloat16 ho1 = __float2bfloat16_rn(o1);
                uint32_t* H = (uint32_t*)(args.Ch[z] + (size_t)row * DMODEL + col);
                uint32_t* L = (uint32_t*)(args.Cl[z] + (size_t)row * DMODEL + col);
                *H = pack_bf16(he0, ho0);
                *L = pack_bf16f(e0 - __bfloat162float(he0),
                                o0 - __bfloat162float(ho0));
                H = (uint32_t*)(args.Ch[z] + (size_t)(row + 8) * DMODEL + col);
                L = (uint32_t*)(args.Cl[z] + (size_t)(row + 8) * DMODEL + col);
                *H = pack_bf16(he1, ho1);
                *L = pack_bf16f(e1 - __bfloat162float(he1),
                                o1 - __bfloat162float(ho1));
            }
        }
    }
}

// ========================================================================
// Flash attention, bf16 HMMA 3-term, causal. BM=BN=64, 128 thr (4 warps).
// Warp w owns q rows 16w..16w+15; softmax reductions stay in-warp.
// ========================================================================
#define FLDB 144   // bytes per smem tile row (72 bf16)

__global__ __launch_bounds__(128) void flash_hmma(
    const __nv_bfloat16* __restrict__ Qhg, const __nv_bfloat16* __restrict__ Qlg,
    const __nv_bfloat16* __restrict__ Khg, const __nv_bfloat16* __restrict__ Klg,
    const __nv_bfloat16* __restrict__ Vhg, const __nv_bfloat16* __restrict__ Vlg,
    __nv_bfloat16* __restrict__ Ohg, __nv_bfloat16* __restrict__ Olg) {
    __shared__ __nv_bfloat16 sKh[64 * 72], sKl[64 * 72];
    __shared__ __nv_bfloat16 sVh[64 * 72], sVl[64 * 72];

    const int qt  = gridDim.x - 1 - blockIdx.x;
    const int h   = blockIdx.y;
    const int b   = blockIdx.z;
    const int tid = threadIdx.x;
    const int lane = tid & 31;
    const int w    = tid >> 5;
    const size_t base = ((size_t)b * S_LEN) * DMODEL + h * DK;
    const int q0 = qt * 64;

    const int l7  = lane & 7;
    const int l8  = (lane >> 3) & 1;
    const int l16 = lane >> 4;
    const int g   = lane >> 2;
    const int tig = lane & 3;

    const uint32_t sKh_b = smem_u32(sKh), sKl_b = smem_u32(sKl);
    const uint32_t sVh_b = smem_u32(sVh), sVl_b = smem_u32(sVl);

    // ---- stage Q through sKh/sKl, extract A-frags ----
#pragma unroll
    for (int p = 0; p < 4; p++) {
        int f = tid + p * 128;
        int r = f >> 3, c = f & 7;
        *(uint4*)((char*)sKh + r * FLDB + c * 16) =
            *(const uint4*)(Qhg + base + (size_t)(q0 + r) * DMODEL + c * 8);
        *(uint4*)((char*)sKl + r * FLDB + c * 16) =
            *(const uint4*)(Qlg + base + (size_t)(q0 + r) * DMODEL + c * 8);
    }
    __syncthreads();
    uint32_t qha[4][4], qla[4][4];
    {
        const uint32_t ao = (uint32_t)((w * 16 + l7 + l8 * 8) * FLDB + l16 * 16);
#pragma unroll
        for (int ks = 0; ks < 4; ks++) {
            ldmat4(qha[ks], sKh_b + ao + ks * 32);
            ldmat4(qla[ks], sKl_b + ao + ks * 32);
        }
    }
    __syncthreads();

    float o[8][4];
#pragma unroll
    for (int dt = 0; dt < 8; dt++)
#pragma unroll
        for (int e = 0; e < 4; e++) o[dt][e] = 0.f;
    float m0 = -INFINITY, m1 = -INFINITY, li0 = 0.f, li1 = 0.f;

    const uint32_t bo_k = (uint32_t)((l16 * 8 + l7) * FLDB + l8 * 16);
    const uint32_t bo_v = (uint32_t)((l8 * 8 + l7) * FLDB + l16 * 16);

    for (int kt = 0; kt <= qt; kt++) {
        const int k0 = kt * 64;
#pragma unroll
        for (int p = 0; p < 4; p++) {
            int f = tid + p * 128;
            int r = f >> 3, c = f & 7;
            const size_t gk = base + (size_t)(k0 + r) * DMODEL + c * 8;
            *(uint4*)((char*)sKh + r * FLDB + c * 16) = *(const uint4*)(Khg + gk);
            *(uint4*)((char*)sKl + r * FLDB + c * 16) = *(const uint4*)(Klg + gk);
            *(uint4*)((char*)sVh + r * FLDB + c * 16) = *(const uint4*)(Vhg + gk);
            *(uint4*)((char*)sVl + r * FLDB + c * 16) = *(const uint4*)(Vlg + gk);
        }
        __syncthreads();

        // ---- S = Q K^T (3-term) ----
        float s[8][4];
#pragma unroll
        for (int nt = 0; nt < 8; nt++)
#pragma unroll
            for (int e = 0; e < 4; e++) s[nt][e] = 0.f;

#pragma unroll
        for (int ks = 0; ks < 4; ks++) {
#pragma unroll
            for (int np = 0; np < 4; np++) {
                uint32_t th[4], tl[4];
                const uint32_t bo = bo_k + np * (16 * FLDB) + ks * 32;
                ldmat4(th, sKh_b + bo);
                ldmat4(tl, sKl_b + bo);
                mma_bf16(s[2 * np],     qha[ks], th);
                mma_bf16(s[2 * np],     qha[ks], tl);
                mma_bf16(s[2 * np],     qla[ks], th);
                mma_bf16(s[2 * np + 1], qha[ks], th + 2);
                mma_bf16(s[2 * np + 1], qha[ks], tl + 2);
                mma_bf16(s[2 * np + 1], qla[ks], th + 2);
            }
        }

        // ---- softmax (rows 16w+g and 16w+g+8) ----
        const bool diag = (kt == qt);
        const int row0 = 16 * w + g, row1 = row0 + 8;
        float mx0 = -INFINITY, mx1 = -INFINITY;
#pragma unroll
        for (int nt = 0; nt < 8; nt++) {
            const int c0 = nt * 8 + 2 * tig;
#pragma unroll
            for (int e = 0; e < 4; e++) s[nt][e] *= 0.125f;
            if (diag) {
                if (c0     > row0) s[nt][0] = -INFINITY;
                if (c0 + 1 > row0) s[nt][1] = -INFINITY;
                if (c0     > row1) s[nt][2] = -INFINITY;
                if (c0 + 1 > row1) s[nt][3] = -INFINITY;
            }
            mx0 = fmaxf(mx0, fmaxf(s[nt][0], s[nt][1]));
            mx1 = fmaxf(mx1, fmaxf(s[nt][2], s[nt][3]));
        }
#pragma unroll
        for (int off = 1; off <= 2; off <<= 1) {
            mx0 = fmaxf(mx0, __shfl_xor_sync(0xffffffffu, mx0, off));
            mx1 = fmaxf(mx1, __shfl_xor_sync(0xffffffffu, mx1, off));
        }
        const float nm0 = fmaxf(m0, mx0), nm1 = fmaxf(m1, mx1);
        const float cr0 = __expf(m0 - nm0), cr1 = __expf(m1 - nm1);
        m0 = nm0; m1 = nm1;
        float rs0 = 0.f, rs1 = 0.f;
#pragma unroll
        for (int nt = 0; nt < 8; nt++) {
            s[nt][0] = __expf(s[nt][0] - nm0);
            s[nt][1] = __expf(s[nt][1] - nm0);
            s[nt][2] = __expf(s[nt][2] - nm1);
            s[nt][3] = __expf(s[nt][3] - nm1);
            rs0 += s[nt][0] + s[nt][1];
            rs1 += s[nt][2] + s[nt][3];
        }
#pragma unroll
        for (int off = 1; off <= 2; off <<= 1) {
            rs0 += __shfl_xor_sync(0xffffffffu, rs0, off);
            rs1 += __shfl_xor_sync(0xffffffffu, rs1, off);
        }
        li0 = li0 * cr0 + rs0;
        li1 = li1 * cr1 + rs1;
#pragma unroll
        for (int dt = 0; dt < 8; dt++) {
            o[dt][0] *= cr0; o[dt][1] *= cr0;
            o[dt][2] *= cr1; o[dt][3] *= cr1;
        }

        // ---- O += P V (3-term, P split in registers) ----
#pragma unroll
        for (int j = 0; j < 4; j++) {
            uint32_t pha[4], pla[4];
#pragma unroll
            for (int half = 0; half < 2; half++) {
                const int nt = 2 * j + half;
                __nv_bfloat16 b0 = __float2bfloat16_rn(s[nt][0]);
                __nv_bfloat16 b1 = __float2bfloat16_rn(s[nt][1]);
                __nv_bfloat16 b2 = __float2bfloat16_rn(s[nt][2]);
                __nv_bfloat16 b3 = __float2bfloat16_rn(s[nt][3]);
                pha[2 * half + 0] = pack_bf16(b0, b1);
                pha[2 * half + 1] = pack_bf16(b2, b3);
                pla[2 * half + 0] = pack_bf16f(s[nt][0] - __bfloat162float(b0),
                                               s[nt][1] - __bfloat162float(b1));
                pla[2 * half + 1] = pack_bf16f(s[nt][2] - __bfloat162float(b2),
                                               s[nt][3] - __bfloat162float(b3));
            }
#pragma unroll
            for (int np = 0; np < 4; np++) {
                uint32_t tvh[4], tvl[4];
                const uint32_t bo = bo_v + j * (16 * FLDB) + np * 32;
                ldmat4t(tvh, sVh_b + bo);
                ldmat4t(tvl, sVl_b + bo);
                mma_bf16(o[2 * np],     pha, tvh);
                mma_bf16(o[2 * np],     pha, tvl);
                mma_bf16(o[2 * np],     pla, tvh);
                mma_bf16(o[2 * np + 1], pha, tvh + 2);
                mma_bf16(o[2 * np + 1], pha, tvl + 2);
                mma_bf16(o[2 * np + 1], pla, tvh + 2);
            }
        }
        __syncthreads();
    }

    // ---- epilogue: normalize + bf16 hi/lo split store ----
    const float inv0 = 1.0f / li0, inv1 = 1.0f / li1;
    const int row0 = q0 + 16 * w + g;
#pragma unroll
    for (int dt = 0; dt < 8; dt++) {
        const int col = dt * 8 + tig * 2;
        float e0 = o[dt][0] * inv0, o0 = o[dt][1] * inv0;
        float e1 = o[dt][2] * inv1, o1 = o[dt][3] * inv1;
        __nv_bfloat16 he0 = __float2bfloat16_rn(e0);
        __nv_bfloat16 ho0 = __float2bfloat16_rn(o0);
        __nv_bfloat16 he1 = __float2bfloat16_rn(e1);
        __nv_bfloat16 ho1 = __float2bfloat16_rn(o1);
        *(uint32_t*)(Ohg + base + (size_t)row0 * DMODEL + col) =
            pack_bf16(he0, ho0);
        *(uint32_t*)(Olg + base + (size_t)row0 * DMODEL + col) =
            pack_bf16f(e0 - __bfloat162float(he0), o0 - __bfloat162float(ho0));
        *(uint32_t*)(Ohg + base + (size_t)(row0 + 8) * DMODEL + col) =
            pack_bf16(he1, ho1);
        *(uint32_t*)(Olg + base + (size_t)(row0 + 8) * DMODEL + col) =
            pack_bf16f(e1 - __bfloat162float(he1), o1 - __bfloat162float(ho1));
    }
}

// ========================================================================
extern "C" void kernel_launch(void* const* d_in, const int* in_sizes, int n_in,
                              void* d_out, int out_size) {
    (void)in_sizes; (void)n_in; (void)out_size;
    const float* x  = (const float*)d_in[0];
    const float* W[4] = {(const float*)d_in[1], (const float*)d_in[2],
                         (const float*)d_in[3], (const float*)d_in[4]};
    float* out = (float*)d_out;

    __nv_bfloat16 *xh, *xl, *qh, *ql, *kh, *kl, *vh, *vl, *oh, *ol, *wh, *wl;
    cudaGetSymbolAddress((void**)&xh, g_xh);
    cudaGetSymbolAddress((void**)&xl, g_xl);
    cudaGetSymbolAddress((void**)&qh, g_qh);
    cudaGetSymbolAddress((void**)&ql, g_ql);
    cudaGetSymbolAddress((void**)&kh, g_kh);
    cudaGetSymbolAddress((void**)&kl, g_kl);
    cudaGetSymbolAddress((void**)&vh, g_vh);
    cudaGetSymbolAddress((void**)&vl, g_vl);
    cudaGetSymbolAddress((void**)&oh, g_oh);
    cudaGetSymbolAddress((void**)&ol, g_ol);
    cudaGetSymbolAddress((void**)&wh, g_wh);
    cudaGetSymbolAddress((void**)&wl, g_wl);

    const int NX4 = MTOT * DMODEL / 4;
    const int NW4 = DMODEL * DMODEL / 4;
    split_kernel<<<NX4 / 256, 256>>>(x, xh, xl, NX4);
    for (int i = 0; i < 4; i++)
        split_kernel<<<NW4 / 256, 256>>>(W[i], wh + (size_t)i * DMODEL * DMODEL,
                                         wl + (size_t)i * DMODEL * DMODEL, NW4);
    rope_table_kernel<<<(S_LEN * (DK / 2) + 255) / 256, 256>>>();

    // fused QKV projection: Q,K get rope+split; V gets split
    GemmArgs qkv = {};
    qkv.Ah = xh; qkv.Al = xl;
    for (int i = 0; i < 3; i++) {
        qkv.Bh[i] = wh + (size_t)i * DMODEL * DMODEL;
        qkv.Bl[i] = wl + (size_t)i * DMODEL * DMODEL;
    }
    qkv.Ch[0] = qh; qkv.Cl[0] = ql; qkv.mode[0] = 1;
    qkv.Ch[1] = kh; qkv.Cl[1] = kl; qkv.mode[1] = 1;
    qkv.Ch[2] = vh; qkv.Cl[2] = vl; qkv.mode[2] = 2;
    dim3 gq(DMODEL / 128, MTOT / 128, 3);
    gemm_hmma<<<gq, 256>>>(qkv);

    flash_hmma<<<dim3(S_LEN / 64, NHEADS, BATCH), 128>>>(qh, ql, kh, kl, vh, vl,
                                                         oh, ol);

    GemmArgs op = {};
    op.Ah = oh; op.Al = ol;
    op.Bh[0] = wh + 3 * (size_t)DMODEL * DMODEL;
    op.Bl[0] = wl + 3 * (size_t)DMODEL * DMODEL;
    op.Cf[0] = out; op.mode[0] = 0;
    dim3 go(DMODEL / 128, MTOT / 128, 1);
    gemm_hmma<<<go, 256>>>(op);
}